// round 12
// baseline (speedup 1.0000x reference)
#include <cuda_runtime.h>
#include <cuda_fp16.h>
#include <math.h>
#include <stdint.h>

#define BT 32768      // B*T
#define D  512
#define NMOD 3

// ---------------------------------------------------------------------------
// Scratch (__device__ globals; allocation-free rule)
// ---------------------------------------------------------------------------
__device__ __align__(16) __half g_fa[(size_t)NMOD * BT * D];   // fused states fp16
__device__ __align__(16) __half g_wb[(size_t)NMOD * D * D];    // weights fp16
__device__ __align__(16) float  g_p[(size_t)NMOD * BT * D];    // x = S + p + bias

// ---------------------------------------------------------------------------
// helpers
// ---------------------------------------------------------------------------
__device__ __forceinline__ uint32_t smem_to_u32(const void* p) {
    uint32_t a;
    asm("{ .reg .u64 t; cvta.to.shared.u64 t, %1; cvt.u32.u64 %0, t; }" : "=r"(a) : "l"(p));
    return a;
}
__device__ __forceinline__ void cp16(uint32_t s, const void* g) {
    asm volatile("cp.async.cg.shared.global [%0], [%1], 16;" :: "r"(s), "l"(g) : "memory");
}
__device__ __forceinline__ void ldsm4(uint32_t* r, uint32_t addr) {
    asm volatile("ldmatrix.sync.aligned.m8n8.x4.shared.b16 {%0,%1,%2,%3}, [%4];"
                 : "=r"(r[0]), "=r"(r[1]), "=r"(r[2]), "=r"(r[3]) : "r"(addr));
}
__device__ __forceinline__ void mma16816(float* c, const uint32_t* a, const uint32_t* b) {
    asm volatile("mma.sync.aligned.m16n8k16.row.col.f32.f16.f16.f32 "
                 "{%0,%1,%2,%3}, {%4,%5,%6,%7}, {%8,%9}, {%0,%1,%2,%3};"
                 : "+f"(c[0]), "+f"(c[1]), "+f"(c[2]), "+f"(c[3])
                 : "r"(a[0]), "r"(a[1]), "r"(a[2]), "r"(a[3]), "r"(b[0]), "r"(b[1]));
}
__device__ __forceinline__ uint2 pack4h(float4 v) {
    __half2 h01 = __floats2half2_rn(v.x, v.y);
    __half2 h23 = __floats2half2_rn(v.z, v.w);
    uint2 r;
    r.x = *(uint32_t*)&h01; r.y = *(uint32_t*)&h23;
    return r;
}

// ---------------------------------------------------------------------------
// Kernel 1: fusion -> softmax weights + fused states (fp16)
// ---------------------------------------------------------------------------
__global__ void fusion_kernel(const float* __restrict__ s0,
                              const float* __restrict__ s1,
                              const float* __restrict__ s2,
                              float* __restrict__ weights_out) {
    int gwarp = (blockIdx.x * blockDim.x + threadIdx.x) >> 5;
    int lane  = threadIdx.x & 31;
    if (gwarp >= BT) return;

    const float4* p0 = (const float4*)(s0 + (size_t)gwarp * D);
    const float4* p1 = (const float4*)(s1 + (size_t)gwarp * D);
    const float4* p2 = (const float4*)(s2 + (size_t)gwarp * D);

    float4 v0[4], v1[4], v2[4];
#pragma unroll
    for (int q = 0; q < 4; q++) {
        v0[q] = p0[lane + q * 32];
        v1[q] = p1[lane + q * 32];
        v2[q] = p2[lane + q * 32];
    }
    float d[6] = {0.f, 0.f, 0.f, 0.f, 0.f, 0.f};
#pragma unroll
    for (int q = 0; q < 4; q++) {
        float4 a = v0[q], b = v1[q], c = v2[q];
        d[0] += a.x * a.x + a.y * a.y + a.z * a.z + a.w * a.w;
        d[1] += b.x * b.x + b.y * b.y + b.z * b.z + b.w * b.w;
        d[2] += c.x * c.x + c.y * c.y + c.z * c.z + c.w * c.w;
        d[3] += a.x * b.x + a.y * b.y + a.z * b.z + a.w * b.w;
        d[4] += a.x * c.x + a.y * c.y + a.z * c.z + a.w * c.w;
        d[5] += b.x * c.x + b.y * c.y + b.z * c.z + b.w * c.w;
    }
#pragma unroll
    for (int t = 0; t < 6; t++)
#pragma unroll
        for (int off = 16; off > 0; off >>= 1)
            d[t] += __shfl_xor_sync(0xffffffffu, d[t], off);

    float n0 = sqrtf(d[0]), n1 = sqrtf(d[1]), n2 = sqrtf(d[2]);
    float sim[3][3];
    sim[0][0] = d[0] / fmaxf(n0 * n0, 1e-8f) * 2.0f;
    sim[1][1] = d[1] / fmaxf(n1 * n1, 1e-8f) * 2.0f;
    sim[2][2] = d[2] / fmaxf(n2 * n2, 1e-8f) * 2.0f;
    float s01 = d[3] / fmaxf(n0 * n1, 1e-8f) * 2.0f;
    float s02 = d[4] / fmaxf(n0 * n2, 1e-8f) * 2.0f;
    float s12 = d[5] / fmaxf(n1 * n2, 1e-8f) * 2.0f;
    sim[0][1] = s01; sim[1][0] = s01;
    sim[0][2] = s02; sim[2][0] = s02;
    sim[1][2] = s12; sim[2][1] = s12;

    float w[3][3];
#pragma unroll
    for (int i = 0; i < 3; i++) {
        float m  = fmaxf(sim[i][0], fmaxf(sim[i][1], sim[i][2]));
        float e0 = expf(sim[i][0] - m);
        float e1 = expf(sim[i][1] - m);
        float e2 = expf(sim[i][2] - m);
        float inv = 1.0f / (e0 + e1 + e2);
        w[i][0] = e0 * inv; w[i][1] = e1 * inv; w[i][2] = e2 * inv;
    }
    if (lane < 9) {
        int i = lane / 3, j = lane % 3;
        weights_out[((size_t)i * BT + gwarp) * 3 + j] = w[i][j];
    }
#pragma unroll
    for (int i = 0; i < 3; i++) {
        uint2* dst = (uint2*)(g_fa + ((size_t)i * BT + gwarp) * D);
        float w0 = w[i][0], w1 = w[i][1], w2 = w[i][2];
#pragma unroll
        for (int q = 0; q < 4; q++) {
            float4 r;
            r.x = w0 * v0[q].x + w1 * v1[q].x + w2 * v2[q].x;
            r.y = w0 * v0[q].y + w1 * v1[q].y + w2 * v2[q].y;
            r.z = w0 * v0[q].z + w1 * v1[q].z + w2 * v2[q].z;
            r.w = w0 * v0[q].w + w1 * v1[q].w + w2 * v2[q].w;
            dst[lane + q * 32] = pack4h(r);
        }
    }
}

// ---------------------------------------------------------------------------
// Kernel 1b: convert proj_w (fp32) -> fp16
// ---------------------------------------------------------------------------
__global__ void wconv_kernel(const float* __restrict__ pw) {
    int idx = blockIdx.x * blockDim.x + threadIdx.x;
    const int total = NMOD * D * D / 4;
    if (idx >= total) return;
    float4 v = ((const float4*)pw)[idx];
    ((uint2*)g_wb)[idx] = pack4h(v);
}

// ---------------------------------------------------------------------------
// Kernel 2: fp16 mma.sync GEMM (single pass), fp32 accum.
// CTA tile 128x128, warp tile 32x64, K chunk 32, double-buffered cp.async.
// SMEM rows padded to 40 halves (80B). Epilogue: x = acc + bias + S -> g_p.
// ---------------------------------------------------------------------------
#define CHUNK_B   20480              // one buffer: 2 arrays * 128 rows * 80B
#define A_OFF     0
#define B_OFF     10240
#define GEMM_SMEM (2 * CHUNK_B)      // 40960

__global__ void __launch_bounds__(256, 2)
gemm_kernel(const float* __restrict__ s0,
            const float* __restrict__ s1,
            const float* __restrict__ s2,
            const float* __restrict__ proj_b) {
    extern __shared__ char sm[];
    const uint32_t smb = smem_to_u32(sm);
    const int tid  = threadIdx.x;
    const int wid  = tid >> 5;
    const int lane = tid & 31;
    const int n0   = blockIdx.x * 128;
    const int m0   = blockIdx.y * 128;
    const int mod  = blockIdx.z;

    const int wr = wid & 3;        // warp row (32 m-rows each)
    const int wc = wid >> 2;       // warp col (64 n-cols each)

    const uint4* ga = (const uint4*)(g_fa + (size_t)mod * BT * D);
    const uint4* gb = (const uint4*)(g_wb + (size_t)mod * D * D);
    // global row stride = 512 halves = 64 uint4

    auto load_chunk = [&](int ch, int buf) {
        const uint32_t bb = smb + buf * CHUNK_B;
#pragma unroll
        for (int it = 0; it < 2; it++) {
            int idx = tid + it * 256;        // 0..511
            int row = idx >> 2;              // 0..127
            int pc  = idx & 3;               // 16B piece (32 halves per chunk row)
            uint32_t so = bb + row * 80 + pc * 16;
            size_t gaidx = (size_t)(m0 + row) * 64 + ch * 4 + pc;
            size_t gbidx = (size_t)(n0 + row) * 64 + ch * 4 + pc;
            cp16(so + A_OFF, ga + gaidx);
            cp16(so + B_OFF, gb + gbidx);
        }
        asm volatile("cp.async.commit_group;" ::: "memory");
    };

    float acc[2][8][4];
#pragma unroll
    for (int mt = 0; mt < 2; mt++)
#pragma unroll
        for (int nt = 0; nt < 8; nt++)
#pragma unroll
            for (int q = 0; q < 4; q++) acc[mt][nt][q] = 0.f;

    const uint32_t a_row = wr * 32 + (lane & 15);
    const uint32_t a_col = (lane >> 4) << 3;
    const uint32_t b_row = wc * 64 + (((lane >> 4) << 3) | (lane & 7));
    const uint32_t b_col = ((lane >> 3) & 1) << 3;

    load_chunk(0, 0);

    for (int ch = 0; ch < 16; ch++) {
        if (ch < 15) {
            load_chunk(ch + 1, (ch + 1) & 1);
            asm volatile("cp.async.wait_group 1;" ::: "memory");
        } else {
            asm volatile("cp.async.wait_group 0;" ::: "memory");
        }
        __syncthreads();

        const uint32_t bb = smb + (ch & 1) * CHUNK_B;
#pragma unroll
        for (int kk2 = 0; kk2 < 2; kk2++) {
            const uint32_t kk = kk2 * 16;
            uint32_t a[2][4];
#pragma unroll
            for (int mt = 0; mt < 2; mt++)
                ldsm4(a[mt], bb + A_OFF + (a_row + mt * 16) * 80 + (a_col + kk) * 2);
            uint32_t b[4][4];
#pragma unroll
            for (int np = 0; np < 4; np++)
                ldsm4(b[np], bb + B_OFF + (b_row + np * 16) * 80 + (b_col + kk) * 2);
#pragma unroll
            for (int mt = 0; mt < 2; mt++)
#pragma unroll
                for (int nt = 0; nt < 8; nt++)
                    mma16816(acc[mt][nt], a[mt], &b[nt >> 1][(nt & 1) * 2]);
        }
        __syncthreads();
    }

    // epilogue: x = acc + bias + S -> g_p
    const float* Sb = (mod == 0) ? s0 : ((mod == 1) ? s1 : s2);
    const float* pbm = proj_b + (size_t)mod * D;
    float* Cp = g_p + (size_t)mod * BT * D;
    const int gid = lane >> 2, tq = lane & 3;
#pragma unroll
    for (int mt = 0; mt < 2; mt++) {
        const int r0 = m0 + wr * 32 + mt * 16 + gid;
#pragma unroll
        for (int nt = 0; nt < 8; nt++) {
            const int c = n0 + wc * 64 + nt * 8 + tq * 2;
            float2 bv  = *(const float2*)(pbm + c);
            float2 sv0 = *(const float2*)(Sb + (size_t)r0 * D + c);
            float2 sv1 = *(const float2*)(Sb + (size_t)(r0 + 8) * D + c);
            *(float2*)(Cp + (size_t)r0 * D + c) =
                make_float2(acc[mt][nt][0] + bv.x + sv0.x, acc[mt][nt][1] + bv.y + sv0.y);
            *(float2*)(Cp + (size_t)(r0 + 8) * D + c) =
                make_float2(acc[mt][nt][2] + bv.x + sv1.x, acc[mt][nt][3] + bv.y + sv1.y);
        }
    }
}

// ---------------------------------------------------------------------------
// Kernel 3: LayerNorm over precomputed x in g_p; write out.
// ---------------------------------------------------------------------------
__global__ void ln_kernel(const float* __restrict__ ln_g,
                          const float* __restrict__ ln_b,
                          float* __restrict__ out) {
    int row  = (blockIdx.x * blockDim.x + threadIdx.x) >> 5;
    int lane = threadIdx.x & 31;
    if (row >= NMOD * BT) return;
    int i = row / BT;

    const float4* pp = (const float4*)(g_p + (size_t)row * D);

    float4 x[4];
    float sum = 0.f, sumsq = 0.f;
#pragma unroll
    for (int q = 0; q < 4; q++) {
        x[q] = pp[lane + q * 32];
        sum   += x[q].x + x[q].y + x[q].z + x[q].w;
        sumsq += x[q].x * x[q].x + x[q].y * x[q].y + x[q].z * x[q].z + x[q].w * x[q].w;
    }
#pragma unroll
    for (int off = 16; off > 0; off >>= 1) {
        sum   += __shfl_xor_sync(0xffffffffu, sum, off);
        sumsq += __shfl_xor_sync(0xffffffffu, sumsq, off);
    }
    float mu   = sum * (1.0f / D);
    float var  = sumsq * (1.0f / D) - mu * mu;
    float rstd = rsqrtf(var + 1e-5f);

    const float4* gg = (const float4*)(ln_g + (size_t)i * D);
    const float4* be = (const float4*)(ln_b + (size_t)i * D);
    float4* op = (float4*)(out + (size_t)row * D);
#pragma unroll
    for (int q = 0; q < 4; q++) {
        float4 g = gg[lane + q * 32];
        float4 b = be[lane + q * 32];
        float4 r;
        r.x = (x[q].x - mu) * rstd * g.x + b.x;
        r.y = (x[q].y - mu) * rstd * g.y + b.y;
        r.z = (x[q].z - mu) * rstd * g.z + b.z;
        r.w = (x[q].w - mu) * rstd * g.w + b.w;
        op[lane + q * 32] = r;
    }
}

// ---------------------------------------------------------------------------
extern "C" void kernel_launch(void* const* d_in, const int* in_sizes, int n_in,
                              void* d_out, int out_size) {
    const float* s0 = (const float*)d_in[0];
    const float* s1 = (const float*)d_in[1];
    const float* s2 = (const float*)d_in[2];
    const float* pw = (const float*)d_in[3];
    const float* pb = (const float*)d_in[4];
    const float* lg = (const float*)d_in[5];
    const float* lb = (const float*)d_in[6];

    float* out     = (float*)d_out;               // [3,B,T,D]
    float* weights = out + (size_t)NMOD * BT * D; // [3,B,T,3]

    cudaFuncSetAttribute(gemm_kernel,
                         cudaFuncAttributeMaxDynamicSharedMemorySize, GEMM_SMEM);

    fusion_kernel<<<BT / 8, 256>>>(s0, s1, s2, weights);
    wconv_kernel<<<(NMOD * D * D / 4 + 255) / 256, 256>>>(pw);

    dim3 ggrid(D / 128, BT / 128, NMOD);   // (4, 256, 3)
    gemm_kernel<<<ggrid, 256, GEMM_SMEM>>>(s0, s1, s2, pb);

    ln_kernel<<<(NMOD * BT) / 8, 256>>>(lg, lb, out);
}

// round 13
// speedup vs baseline: 1.0029x; 1.0029x over previous
#include <cuda_runtime.h>
#include <cuda_fp16.h>
#include <math.h>
#include <stdint.h>

#define BT 32768      // B*T
#define D  512
#define NMOD 3

// ---------------------------------------------------------------------------
// Scratch (__device__ globals; allocation-free rule)
// ---------------------------------------------------------------------------
__device__ __align__(16) __half g_fa[(size_t)NMOD * BT * D];   // fused states fp16
__device__ __align__(16) __half g_wb[(size_t)NMOD * D * D];    // weights fp16
__device__ __align__(16) float  g_p[(size_t)NMOD * BT * D];    // x = S + p + bias

// ---------------------------------------------------------------------------
// helpers
// ---------------------------------------------------------------------------
__device__ __forceinline__ uint32_t smem_to_u32(const void* p) {
    uint32_t a;
    asm("{ .reg .u64 t; cvta.to.shared.u64 t, %1; cvt.u32.u64 %0, t; }" : "=r"(a) : "l"(p));
    return a;
}
__device__ __forceinline__ void cp16(uint32_t s, const void* g) {
    asm volatile("cp.async.cg.shared.global [%0], [%1], 16;" :: "r"(s), "l"(g) : "memory");
}
__device__ __forceinline__ void ldsm4(uint32_t* r, uint32_t addr) {
    asm volatile("ldmatrix.sync.aligned.m8n8.x4.shared.b16 {%0,%1,%2,%3}, [%4];"
                 : "=r"(r[0]), "=r"(r[1]), "=r"(r[2]), "=r"(r[3]) : "r"(addr));
}
__device__ __forceinline__ void mma16816(float* c, const uint32_t* a, const uint32_t* b) {
    asm volatile("mma.sync.aligned.m16n8k16.row.col.f32.f16.f16.f32 "
                 "{%0,%1,%2,%3}, {%4,%5,%6,%7}, {%8,%9}, {%0,%1,%2,%3};"
                 : "+f"(c[0]), "+f"(c[1]), "+f"(c[2]), "+f"(c[3])
                 : "r"(a[0]), "r"(a[1]), "r"(a[2]), "r"(a[3]), "r"(b[0]), "r"(b[1]));
}
__device__ __forceinline__ uint2 pack4h(float4 v) {
    __half2 h01 = __floats2half2_rn(v.x, v.y);
    __half2 h23 = __floats2half2_rn(v.z, v.w);
    uint2 r;
    r.x = *(uint32_t*)&h01; r.y = *(uint32_t*)&h23;
    return r;
}

// ---------------------------------------------------------------------------
// Kernel 1: fusion -> softmax weights + fused states (fp16)
// ---------------------------------------------------------------------------
__global__ void fusion_kernel(const float* __restrict__ s0,
                              const float* __restrict__ s1,
                              const float* __restrict__ s2,
                              float* __restrict__ weights_out) {
    int gwarp = (blockIdx.x * blockDim.x + threadIdx.x) >> 5;
    int lane  = threadIdx.x & 31;
    if (gwarp >= BT) return;

    const float4* p0 = (const float4*)(s0 + (size_t)gwarp * D);
    const float4* p1 = (const float4*)(s1 + (size_t)gwarp * D);
    const float4* p2 = (const float4*)(s2 + (size_t)gwarp * D);

    float4 v0[4], v1[4], v2[4];
#pragma unroll
    for (int q = 0; q < 4; q++) {
        v0[q] = p0[lane + q * 32];
        v1[q] = p1[lane + q * 32];
        v2[q] = p2[lane + q * 32];
    }
    float d[6] = {0.f, 0.f, 0.f, 0.f, 0.f, 0.f};
#pragma unroll
    for (int q = 0; q < 4; q++) {
        float4 a = v0[q], b = v1[q], c = v2[q];
        d[0] += a.x * a.x + a.y * a.y + a.z * a.z + a.w * a.w;
        d[1] += b.x * b.x + b.y * b.y + b.z * b.z + b.w * b.w;
        d[2] += c.x * c.x + c.y * c.y + c.z * c.z + c.w * c.w;
        d[3] += a.x * b.x + a.y * b.y + a.z * b.z + a.w * b.w;
        d[4] += a.x * c.x + a.y * c.y + a.z * c.z + a.w * c.w;
        d[5] += b.x * c.x + b.y * c.y + b.z * c.z + b.w * c.w;
    }
#pragma unroll
    for (int t = 0; t < 6; t++)
#pragma unroll
        for (int off = 16; off > 0; off >>= 1)
            d[t] += __shfl_xor_sync(0xffffffffu, d[t], off);

    float n0 = sqrtf(d[0]), n1 = sqrtf(d[1]), n2 = sqrtf(d[2]);
    float sim[3][3];
    sim[0][0] = d[0] / fmaxf(n0 * n0, 1e-8f) * 2.0f;
    sim[1][1] = d[1] / fmaxf(n1 * n1, 1e-8f) * 2.0f;
    sim[2][2] = d[2] / fmaxf(n2 * n2, 1e-8f) * 2.0f;
    float s01 = d[3] / fmaxf(n0 * n1, 1e-8f) * 2.0f;
    float s02 = d[4] / fmaxf(n0 * n2, 1e-8f) * 2.0f;
    float s12 = d[5] / fmaxf(n1 * n2, 1e-8f) * 2.0f;
    sim[0][1] = s01; sim[1][0] = s01;
    sim[0][2] = s02; sim[2][0] = s02;
    sim[1][2] = s12; sim[2][1] = s12;

    float w[3][3];
#pragma unroll
    for (int i = 0; i < 3; i++) {
        float m  = fmaxf(sim[i][0], fmaxf(sim[i][1], sim[i][2]));
        float e0 = expf(sim[i][0] - m);
        float e1 = expf(sim[i][1] - m);
        float e2 = expf(sim[i][2] - m);
        float inv = 1.0f / (e0 + e1 + e2);
        w[i][0] = e0 * inv; w[i][1] = e1 * inv; w[i][2] = e2 * inv;
    }
    if (lane < 9) {
        int i = lane / 3, j = lane % 3;
        weights_out[((size_t)i * BT + gwarp) * 3 + j] = w[i][j];
    }
#pragma unroll
    for (int i = 0; i < 3; i++) {
        uint2* dst = (uint2*)(g_fa + ((size_t)i * BT + gwarp) * D);
        float w0 = w[i][0], w1 = w[i][1], w2 = w[i][2];
#pragma unroll
        for (int q = 0; q < 4; q++) {
            float4 r;
            r.x = w0 * v0[q].x + w1 * v1[q].x + w2 * v2[q].x;
            r.y = w0 * v0[q].y + w1 * v1[q].y + w2 * v2[q].y;
            r.z = w0 * v0[q].z + w1 * v1[q].z + w2 * v2[q].z;
            r.w = w0 * v0[q].w + w1 * v1[q].w + w2 * v2[q].w;
            dst[lane + q * 32] = pack4h(r);
        }
    }
}

// ---------------------------------------------------------------------------
// Kernel 1b: convert proj_w (fp32) -> fp16
// ---------------------------------------------------------------------------
__global__ void wconv_kernel(const float* __restrict__ pw) {
    int idx = blockIdx.x * blockDim.x + threadIdx.x;
    const int total = NMOD * D * D / 4;
    if (idx >= total) return;
    float4 v = ((const float4*)pw)[idx];
    ((uint2*)g_wb)[idx] = pack4h(v);
}

// ---------------------------------------------------------------------------
// Kernel 2: fp16 mma.sync GEMM (single pass), fp32 accum.
// CTA tile 128x128, warp tile 32x64, K chunk 32, double-buffered cp.async.
// SMEM rows padded to 40 halves (80B). Epilogue: x = acc + bias + S -> g_p.
// ---------------------------------------------------------------------------
#define CHUNK_B   20480              // one buffer: 2 arrays * 128 rows * 80B
#define A_OFF     0
#define B_OFF     10240
#define GEMM_SMEM (2 * CHUNK_B)      // 40960

__global__ void __launch_bounds__(256, 2)
gemm_kernel(const float* __restrict__ s0,
            const float* __restrict__ s1,
            const float* __restrict__ s2,
            const float* __restrict__ proj_b) {
    extern __shared__ char sm[];
    const uint32_t smb = smem_to_u32(sm);
    const int tid  = threadIdx.x;
    const int wid  = tid >> 5;
    const int lane = tid & 31;
    const int n0   = blockIdx.x * 128;
    const int m0   = blockIdx.y * 128;
    const int mod  = blockIdx.z;

    const int wr = wid & 3;        // warp row (32 m-rows each)
    const int wc = wid >> 2;       // warp col (64 n-cols each)

    const uint4* ga = (const uint4*)(g_fa + (size_t)mod * BT * D);
    const uint4* gb = (const uint4*)(g_wb + (size_t)mod * D * D);
    // global row stride = 512 halves = 64 uint4

    auto load_chunk = [&](int ch, int buf) {
        const uint32_t bb = smb + buf * CHUNK_B;
#pragma unroll
        for (int it = 0; it < 2; it++) {
            int idx = tid + it * 256;        // 0..511
            int row = idx >> 2;              // 0..127
            int pc  = idx & 3;               // 16B piece (32 halves per chunk row)
            uint32_t so = bb + row * 80 + pc * 16;
            size_t gaidx = (size_t)(m0 + row) * 64 + ch * 4 + pc;
            size_t gbidx = (size_t)(n0 + row) * 64 + ch * 4 + pc;
            cp16(so + A_OFF, ga + gaidx);
            cp16(so + B_OFF, gb + gbidx);
        }
        asm volatile("cp.async.commit_group;" ::: "memory");
    };

    float acc[2][8][4];
#pragma unroll
    for (int mt = 0; mt < 2; mt++)
#pragma unroll
        for (int nt = 0; nt < 8; nt++)
#pragma unroll
            for (int q = 0; q < 4; q++) acc[mt][nt][q] = 0.f;

    const uint32_t a_row = wr * 32 + (lane & 15);
    const uint32_t a_col = (lane >> 4) << 3;
    const uint32_t b_row = wc * 64 + (((lane >> 4) << 3) | (lane & 7));
    const uint32_t b_col = ((lane >> 3) & 1) << 3;

    load_chunk(0, 0);

    for (int ch = 0; ch < 16; ch++) {
        if (ch < 15) {
            load_chunk(ch + 1, (ch + 1) & 1);
            asm volatile("cp.async.wait_group 1;" ::: "memory");
        } else {
            asm volatile("cp.async.wait_group 0;" ::: "memory");
        }
        __syncthreads();

        const uint32_t bb = smb + (ch & 1) * CHUNK_B;
#pragma unroll
        for (int kk2 = 0; kk2 < 2; kk2++) {
            const uint32_t kk = kk2 * 16;
            uint32_t a[2][4];
#pragma unroll
            for (int mt = 0; mt < 2; mt++)
                ldsm4(a[mt], bb + A_OFF + (a_row + mt * 16) * 80 + (a_col + kk) * 2);
            uint32_t b[4][4];
#pragma unroll
            for (int np = 0; np < 4; np++)
                ldsm4(b[np], bb + B_OFF + (b_row + np * 16) * 80 + (b_col + kk) * 2);
#pragma unroll
            for (int mt = 0; mt < 2; mt++)
#pragma unroll
                for (int nt = 0; nt < 8; nt++)
                    mma16816(acc[mt][nt], a[mt], &b[nt >> 1][(nt & 1) * 2]);
        }
        __syncthreads();
    }

    // epilogue: x = acc + bias + S -> g_p
    const float* Sb = (mod == 0) ? s0 : ((mod == 1) ? s1 : s2);
    const float* pbm = proj_b + (size_t)mod * D;
    float* Cp = g_p + (size_t)mod * BT * D;
    const int gid = lane >> 2, tq = lane & 3;
#pragma unroll
    for (int mt = 0; mt < 2; mt++) {
        const int r0 = m0 + wr * 32 + mt * 16 + gid;
#pragma unroll
        for (int nt = 0; nt < 8; nt++) {
            const int c = n0 + wc * 64 + nt * 8 + tq * 2;
            float2 bv  = *(const float2*)(pbm + c);
            float2 sv0 = *(const float2*)(Sb + (size_t)r0 * D + c);
            float2 sv1 = *(const float2*)(Sb + (size_t)(r0 + 8) * D + c);
            *(float2*)(Cp + (size_t)r0 * D + c) =
                make_float2(acc[mt][nt][0] + bv.x + sv0.x, acc[mt][nt][1] + bv.y + sv0.y);
            *(float2*)(Cp + (size_t)(r0 + 8) * D + c) =
                make_float2(acc[mt][nt][2] + bv.x + sv1.x, acc[mt][nt][3] + bv.y + sv1.y);
        }
    }
}

// ---------------------------------------------------------------------------
// Kernel 3: LayerNorm over precomputed x in g_p; write out.
// ---------------------------------------------------------------------------
__global__ void ln_kernel(const float* __restrict__ ln_g,
                          const float* __restrict__ ln_b,
                          float* __restrict__ out) {
    int row  = (blockIdx.x * blockDim.x + threadIdx.x) >> 5;
    int lane = threadIdx.x & 31;
    if (row >= NMOD * BT) return;
    int i = row / BT;

    const float4* pp = (const float4*)(g_p + (size_t)row * D);

    float4 x[4];
    float sum = 0.f, sumsq = 0.f;
#pragma unroll
    for (int q = 0; q < 4; q++) {
        x[q] = pp[lane + q * 32];
        sum   += x[q].x + x[q].y + x[q].z + x[q].w;
        sumsq += x[q].x * x[q].x + x[q].y * x[q].y + x[q].z * x[q].z + x[q].w * x[q].w;
    }
#pragma unroll
    for (int off = 16; off > 0; off >>= 1) {
        sum   += __shfl_xor_sync(0xffffffffu, sum, off);
        sumsq += __shfl_xor_sync(0xffffffffu, sumsq, off);
    }
    float mu   = sum * (1.0f / D);
    float var  = sumsq * (1.0f / D) - mu * mu;
    float rstd = rsqrtf(var + 1e-5f);

    const float4* gg = (const float4*)(ln_g + (size_t)i * D);
    const float4* be = (const float4*)(ln_b + (size_t)i * D);
    float4* op = (float4*)(out + (size_t)row * D);
#pragma unroll
    for (int q = 0; q < 4; q++) {
        float4 g = gg[lane + q * 32];
        float4 b = be[lane + q * 32];
        float4 r;
        r.x = (x[q].x - mu) * rstd * g.x + b.x;
        r.y = (x[q].y - mu) * rstd * g.y + b.y;
        r.z = (x[q].z - mu) * rstd * g.z + b.z;
        r.w = (x[q].w - mu) * rstd * g.w + b.w;
        op[lane + q * 32] = r;
    }
}

// ---------------------------------------------------------------------------
extern "C" void kernel_launch(void* const* d_in, const int* in_sizes, int n_in,
                              void* d_out, int out_size) {
    const float* s0 = (const float*)d_in[0];
    const float* s1 = (const float*)d_in[1];
    const float* s2 = (const float*)d_in[2];
    const float* pw = (const float*)d_in[3];
    const float* pb = (const float*)d_in[4];
    const float* lg = (const float*)d_in[5];
    const float* lb = (const float*)d_in[6];

    float* out     = (float*)d_out;               // [3,B,T,D]
    float* weights = out + (size_t)NMOD * BT * D; // [3,B,T,3]

    cudaFuncSetAttribute(gemm_kernel,
                         cudaFuncAttributeMaxDynamicSharedMemorySize, GEMM_SMEM);

    fusion_kernel<<<BT / 8, 256>>>(s0, s1, s2, weights);
    wconv_kernel<<<(NMOD * D * D / 4 + 255) / 256, 256>>>(pw);

    dim3 ggrid(D / 128, BT / 128, NMOD);   // (4, 256, 3)
    gemm_kernel<<<ggrid, 256, GEMM_SMEM>>>(s0, s1, s2, pb);

    ln_kernel<<<(NMOD * BT) / 8, 256>>>(lg, lb, out);
}